// round 15
// baseline (speedup 1.0000x reference)
#include <cuda_runtime.h>
#include <stdint.h>
#include <math.h>

#define BATCH 32
#define SEQ   512
#define DEMB  768
#define DK    512
#define DV    1024
#define NHEAD 8

#define OUT_ELEMS  ((size_t)BATCH*SEQ*DEMB)          // 12,582,912
#define ATTN_ELEMS ((size_t)BATCH*NHEAD*SEQ*SEQ)     // 67,108,864
#define MASK_ELEMS (BATCH*SEQ)                       // 16,384

// ---------------- scratch (static __device__, no runtime allocs) ----------
__device__ float g_q1 [(size_t)BATCH*SEQ*DK];
__device__ float g_k1 [(size_t)BATCH*SEQ*DK];
__device__ float g_q1c[(size_t)BATCH*SEQ*DK];
__device__ float g_k1c[(size_t)BATCH*SEQ*DK];
__device__ float g_v1 [(size_t)BATCH*SEQ*DV];
__device__ float g_ctx[(size_t)BATCH*SEQ*DV];
__device__ float g_fc [(size_t)BATCH*SEQ*DEMB];
__device__ uint8_t g_m1c[MASK_ELEMS];
__device__ uint8_t g_m2c[MASK_ELEMS];
__device__ float g_attn_fallback[ATTN_ELEMS];

// ---------------- mask canonicalization ------------------------------------
__device__ __forceinline__ int detect_mask_dtype(const uint32_t* w) {
    bool low_bf16 = false, f32 = false, topbytes = false;
    #pragma unroll 8
    for (int i = 0; i < 64; i++) {
        uint32_t x = w[i];
        if ((x & 0xFFFFu) == 0x3F80u) low_bf16 = true;
        if (x == 0x3F800000u)         f32 = true;
        if (x & 0xFFFFFF00u)          topbytes = true;
    }
    if (low_bf16) return 3;
    if (f32)      return 2;
    if (topbytes) return 1;
    return 0;                 // int32
}

__global__ void canonicalize_masks_kernel(const void* m1, const void* m2) {
    const int i = blockIdx.x * blockDim.x + threadIdx.x;
    const int code1 = detect_mask_dtype((const uint32_t*)m1);
    const int code2 = detect_mask_dtype((const uint32_t*)m2);

    uint8_t v1, v2;
    switch (code1) {
        case 0:  v1 = ((const int32_t*) m1)[i] != 0; break;
        case 1:  v1 = ((const uint8_t*) m1)[i] != 0; break;
        case 2:  v1 = ((const uint32_t*)m1)[i] != 0; break;
        default: v1 = ((const uint16_t*)m1)[i] != 0; break;
    }
    switch (code2) {
        case 0:  v2 = ((const int32_t*) m2)[i] != 0; break;
        case 1:  v2 = ((const uint8_t*) m2)[i] != 0; break;
        case 2:  v2 = ((const uint32_t*)m2)[i] != 0; break;
        default: v2 = ((const uint16_t*)m2)[i] != 0; break;
    }
    g_m1c[i] = v1;
    g_m2c[i] = v2;
}

// ---------------- shared PTX helpers ----------------------------------------
__device__ __forceinline__ void cpa16(uint32_t dst, const void* src) {
    asm volatile("cp.async.cg.shared.global [%0], [%1], 16;" :: "r"(dst), "l"(src));
}
__device__ __forceinline__ void cpa_commit() {
    asm volatile("cp.async.commit_group;");
}
__device__ __forceinline__ void cpa_wait1() {
    asm volatile("cp.async.wait_group 1;");
}

__device__ __forceinline__ void mma_tf32(float c[4],
    uint32_t a0, uint32_t a1, uint32_t a2, uint32_t a3,
    uint32_t b0, uint32_t b1)
{
    asm volatile(
        "mma.sync.aligned.m16n8k8.row.col.f32.tf32.tf32.f32 "
        "{%0,%1,%2,%3}, {%4,%5,%6,%7}, {%8,%9}, {%0,%1,%2,%3};"
        : "+f"(c[0]), "+f"(c[1]), "+f"(c[2]), "+f"(c[3])
        : "r"(a0), "r"(a1), "r"(a2), "r"(a3), "r"(b0), "r"(b1));
}

// ---------------- TF32 tensor-core batched GEMM (BK=32, 3-stage) ------------
// C[z] = alpha * A[z] @ B[z] (+rowBias) (+resid), row-major, fp32 accumulate.
// TRB=false: B is K x N. TRB=true: B is N x K (C = A @ B^T).
// Requires M,N % 128 == 0, K % 32 == 0, K >= 64 (all call sites comply).
// Block 128x128xBK32, 128 threads, 4 warps of 64x64.
// Each BK=32 stage = two verified BK=16 sub-tile layouts back-to-back:
//   A / B(TR): [row][16] packed, chunk swizzle ch' = ch ^ ((row>>1)&3)
//   B(nonTR):  [k][128] packed, chunk swizzle  cn' = cn ^ (2*(k&3))
// 3-stage ring (dynamic smem, 32KB/stage), 2 tiles in flight, wait_group 1,
// ONE __syncthreads per BK=32 tile -> 64 MMAs between syncs (2x R13).
#define GT_STAGE_W 8192              // words per stage (A 4096 + B 4096)
#define GT_SMEM_BYTES (3 * GT_STAGE_W * 4)

template<bool TRB>
__global__ void __launch_bounds__(128, 2) gemm_tc(
    int M, int N, int K,
    const float* __restrict__ A, int lda, long long sAb, long long sAh,
    const float* __restrict__ B, int ldb, long long sBb, long long sBh,
    float* __restrict__ C, int ldc, long long sCb, long long sCh,
    int H, float alpha,
    const float* __restrict__ rowBias,
    const float* __restrict__ resid, int ldr)
{
    extern __shared__ __align__(16) uint32_t dsm[];
    uint32_t* Asm = dsm;                         // stage s at s*GT_STAGE_W
    uint32_t* Bsm = dsm + 4096;                  // stage s at s*GT_STAGE_W + 4096

    const int z = blockIdx.z;
    const int b = z / H, h = z % H;
    A += b * sAb + h * sAh;
    B += b * sBb + h * sBh;
    C += b * sCb + h * sCh;

    const int m0 = blockIdx.y * 128;
    const int n0 = blockIdx.x * 128;
    const int tid  = threadIdx.x;
    const int wid  = tid >> 5;
    const int lane = tid & 31;
    const int wm = wid & 1;
    const int wn = wid >> 1;
    const int grp = lane >> 2;
    const int tg  = lane & 3;

    const uint32_t asAddr = (uint32_t)__cvta_generic_to_shared(Asm);
    const uint32_t bsAddr = (uint32_t)__cvta_generic_to_shared(Bsm);

    float acc[4][8][4] = {};

    // loader: 8 cpa16/thread per operand per BK=32 tile
    auto load_tile = [&](int s, int k0) {
        const uint32_t sb = (uint32_t)(s * GT_STAGE_W);
        #pragma unroll
        for (int j = 0; j < 8; j++) {
            const int c = tid + j * 128;          // 0..1023
            const int kt = c >> 9;                // sub-tile 0/1
            const int pos = c & 511;
            const int row = pos >> 2, ch = pos & 3;
            const uint32_t adst = sb + (uint32_t)(kt * 2048 + row * 16 +
                                    ((ch ^ ((row >> 1) & 3)) << 2));
            cpa16(asAddr + adst * 4u,
                  A + (size_t)(m0 + row) * lda + k0 + kt * 16 + ch * 4);
            if (TRB) {
                cpa16(bsAddr + adst * 4u,
                      B + (size_t)(n0 + row) * ldb + k0 + kt * 16 + ch * 4);
            } else {
                const int bk = pos >> 5, bcn = pos & 31;
                const uint32_t bdst = sb + (uint32_t)(kt * 2048 + bk * 128 +
                                        ((bcn ^ (2 * (bk & 3))) << 2));
                cpa16(bsAddr + bdst * 4u,
                      B + (size_t)(k0 + kt * 16 + bk) * ldb + n0 + bcn * 4);
            }
        }
    };

    // fragment address bases (hoisted; same formulas as R13)
    int abase[4][2], aswz[4][2];
    #pragma unroll
    for (int mi = 0; mi < 4; mi++) {
        const int mr0 = wm * 64 + mi * 16 + grp;
        const int mr1 = mr0 + 8;
        abase[mi][0] = mr0 * 16 + tg;  aswz[mi][0] = (mr0 >> 1) & 3;
        abase[mi][1] = mr1 * 16 + tg;  aswz[mi][1] = (mr1 >> 1) & 3;
    }
    int bbaseT[8], bswzT[8], bqF[8];
    #pragma unroll
    for (int nj = 0; nj < 8; nj++) {
        const int nr = wn * 64 + nj * 8 + grp;
        bbaseT[nj] = nr * 16 + tg;  bswzT[nj] = (nr >> 1) & 3;
        const int cn = nr >> 2, nl = nr & 3;
        bqF[nj] = ((cn ^ (2 * tg)) << 2) + nl;
    }

    const int nIter = K >> 5;   // >= 2 at all call sites

    load_tile(0, 0);  cpa_commit();
    load_tile(1, 32); cpa_commit();

    int stage = 0;
    for (int it = 0; it < nIter; it++) {
        cpa_wait1();              // tile `it` resident for this thread
        __syncthreads();          // visible to all; compute(it-1) done by all
                                  // -> stage (it+2)%3 == (it-1)%3 safe to reuse

        const int nt = it + 2;    // uniform commit cadence (empty ok)
        int nstage = stage + 2; if (nstage >= 3) nstage -= 3;
        if (nt < nIter) load_tile(nstage, nt * 32);
        cpa_commit();

        const uint32_t* AbT = Asm + stage * GT_STAGE_W;
        const uint32_t* BbT = Bsm + stage * GT_STAGE_W;

        #pragma unroll
        for (int kt = 0; kt < 2; kt++) {
            const uint32_t* Ab = AbT + kt * 2048;
            const uint32_t* Bb = BbT + kt * 2048;
            #pragma unroll
            for (int kk = 0; kk < 2; kk++) {
                const int ko = kk * 8;
                const int c0 = kk * 2;
                uint32_t af[4][4];
                #pragma unroll
                for (int mi = 0; mi < 4; mi++) {
                    af[mi][0] = Ab[abase[mi][0] + ((c0 ^ aswz[mi][0]) << 2)];
                    af[mi][1] = Ab[abase[mi][1] + ((c0 ^ aswz[mi][1]) << 2)];
                    af[mi][2] = Ab[abase[mi][0] + (((c0 + 1) ^ aswz[mi][0]) << 2)];
                    af[mi][3] = Ab[abase[mi][1] + (((c0 + 1) ^ aswz[mi][1]) << 2)];
                }
                uint32_t bf[8][2];
                #pragma unroll
                for (int nj = 0; nj < 8; nj++) {
                    if (TRB) {
                        bf[nj][0] = Bb[bbaseT[nj] + ((c0 ^ bswzT[nj]) << 2)];
                        bf[nj][1] = Bb[bbaseT[nj] + (((c0 + 1) ^ bswzT[nj]) << 2)];
                    } else {
                        bf[nj][0] = Bb[(ko + tg) * 128 + bqF[nj]];
                        bf[nj][1] = Bb[(ko + tg + 4) * 128 + bqF[nj]];
                    }
                }
                #pragma unroll
                for (int mi = 0; mi < 4; mi++)
                    #pragma unroll
                    for (int nj = 0; nj < 8; nj++)
                        mma_tf32(acc[mi][nj],
                                 af[mi][0], af[mi][1], af[mi][2], af[mi][3],
                                 bf[nj][0], bf[nj][1]);
            }
        }
        if (++stage == 3) stage = 0;
    }

    // ---- epilogue
    #pragma unroll
    for (int mi = 0; mi < 4; mi++) {
        const int row = m0 + wm * 64 + mi * 16 + grp;
        const float bias0 = rowBias ? rowBias[row] : 0.0f;
        const float bias1 = rowBias ? rowBias[row + 8] : 0.0f;
        #pragma unroll
        for (int nj = 0; nj < 8; nj++) {
            const int col = n0 + wn * 64 + nj * 8 + tg * 2;
            float2 o0, o1;
            o0.x = acc[mi][nj][0] * alpha + bias0;
            o0.y = acc[mi][nj][1] * alpha + bias0;
            o1.x = acc[mi][nj][2] * alpha + bias1;
            o1.y = acc[mi][nj][3] * alpha + bias1;
            if (resid) {
                float2 r0 = *(const float2*)(resid + (size_t)row * ldr + col);
                float2 r1 = *(const float2*)(resid + (size_t)(row + 8) * ldr + col);
                o0.x += r0.x; o0.y += r0.y;
                o1.x += r1.x; o1.y += r1.y;
            }
            *(float2*)(C + (size_t)row * ldc + col)       = o0;
            *(float2*)(C + (size_t)(row + 8) * ldc + col) = o1;
        }
    }
}

// ---------------- fused scores + mask + softmax (unchanged from R14) --------
#define FS_SA  0
#define FS_SB  8192
#define FS_SP  24576
#define FS_SI  24832
#define FS_SQM 24960
#define FS_SKM 24992
#define FS_SMEM_BYTES (25120 * 4)

__device__ __forceinline__ void cpa_wait1_fs() {
    asm volatile("cp.async.wait_group 1;");
}

__global__ void __launch_bounds__(128, 2) fused_scores(
    const float* __restrict__ Qc, const float* __restrict__ Kc,
    float* __restrict__ attn, float inv_temp)
{
    extern __shared__ __align__(16) uint32_t fs[];
    const int z = blockIdx.z;            // b*8+h
    const int b = z >> 3, h = z & 7;
    const int m0r = blockIdx.y * 128;
    const float* Ag = Qc + (size_t)b * (SEQ * DK) + (size_t)h * 64;
    const float* Bg = Kc + (size_t)b * (SEQ * DK) + (size_t)h * 64;
    float* attnS = attn + (size_t)z * (SEQ * SEQ);

    const int tid = threadIdx.x, wid = tid >> 5, lane = tid & 31;
    const int wm = wid & 1, wn = wid >> 1;
    const int grp = lane >> 2, tg = lane & 3;

    const uint32_t sbase = (uint32_t)__cvta_generic_to_shared(fs);

    #pragma unroll
    for (int j = 0; j < 16; j++) {
        const int c = tid + j * 128;
        const int kt = c >> 9, row = (c >> 2) & 127, ch = c & 3;
        const uint32_t dst = (uint32_t)(FS_SA + kt * 2048 + row * 16 +
                                        ((ch ^ ((row >> 1) & 3)) << 2));
        cpa16(sbase + dst * 4u, Ag + (size_t)(m0r + row) * DK + kt * 16 + ch * 4);
    }
    #pragma unroll
    for (int j = 0; j < 16; j++) {
        const int c = tid + j * 128;
        const int kt = c >> 9, row = (c >> 2) & 127, ch = c & 3;
        const uint32_t dst = (uint32_t)(FS_SB + kt * 2048 + row * 16 +
                                        ((ch ^ ((row >> 1) & 3)) << 2));
        cpa16(sbase + dst * 4u, Bg + (size_t)row * DK + kt * 16 + ch * 4);
    }
    cpa_commit();

    ((uint8_t*)(fs + FS_SQM))[tid] = g_m1c[b * SEQ + m0r + tid];
    fs[FS_SP + tid] = 0;
    fs[FS_SP + 128 + tid] = 0;
    {
        uint8_t* km = (uint8_t*)(fs + FS_SKM);
        #pragma unroll
        for (int j = 0; j < 4; j++) km[tid + j * 128] = g_m2c[b * SEQ + tid + j * 128];
    }

    int abase[4][2], aswz[4][2];
    #pragma unroll
    for (int mi = 0; mi < 4; mi++) {
        const int mr0 = wm * 64 + mi * 16 + grp;
        const int mr1 = mr0 + 8;
        abase[mi][0] = mr0 * 16 + tg;  aswz[mi][0] = (mr0 >> 1) & 3;
        abase[mi][1] = mr1 * 16 + tg;  aswz[mi][1] = (mr1 >> 1) & 3;
    }
    int bbaseT[8], bswzT[8];
    #pragma unroll
    for (int nj = 0; nj < 8; nj++) {
        const int nr = wn * 64 + nj * 8 + grp;
        bbaseT[nj] = nr * 16 + tg;  bswzT[nj] = (nr >> 1) & 3;
    }

    float* SPf = (float*)(fs + FS_SP);
    const uint8_t* qm = (const uint8_t*)(fs + FS_SQM);
    const uint8_t* km = (const uint8_t*)(fs + FS_SKM);

    for (int sub = 0; sub < 4; sub++) {
        if (sub < 3) {
            const int n0n = (sub + 1) * 128;
            const int bufn = (sub + 1) & 1;
            #pragma unroll
            for (int j = 0; j < 16; j++) {
                const int c = tid + j * 128;
                const int kt = c >> 9, row = (c >> 2) & 127, ch = c & 3;
                const uint32_t dst = (uint32_t)(FS_SB + bufn * 8192 + kt * 2048 +
                                                row * 16 + ((ch ^ ((row >> 1) & 3)) << 2));
                cpa16(sbase + dst * 4u, Bg + (size_t)(n0n + row) * DK + kt * 16 + ch * 4);
            }
        }
        cpa_commit();
        cpa_wait1_fs();
        __syncthreads();

        float acc[4][8][4] = {};
        const int buf = sub & 1;

        #pragma unroll
        for (int kt = 0; kt < 4; kt++) {
            const uint32_t* Ab = fs + FS_SA + kt * 2048;
            const uint32_t* Bb = fs + FS_SB + buf * 8192 + kt * 2048;
            #pragma unroll
            for (int kk = 0; kk < 2; kk++) {
                const int c0 = kk * 2;
                uint32_t af[4][4];
                #pragma unroll
                for (int mi = 0; mi < 4; mi++) {
                    af[mi][0] = Ab[abase[mi][0] + ((c0 ^ aswz[mi][0]) << 2)];
                    af[mi][1] = Ab[abase[mi][1] + ((c0 ^ aswz[mi][1]) << 2)];
                    af[mi][2] = Ab[abase[mi][0] + (((c0 + 1) ^ aswz[mi][0]) << 2)];
                    af[mi][3] = Ab[abase[mi][1] + (((c0 + 1) ^ aswz[mi][1]) << 2)];
                }
                uint32_t bf[8][2];
                #pragma unroll
                for (int nj = 0; nj < 8; nj++) {
                    bf[nj][0] = Bb[bbaseT[nj] + ((c0 ^ bswzT[nj]) << 2)];
                    bf[nj][1] = Bb[bbaseT[nj] + (((c0 + 1) ^ bswzT[nj]) << 2)];
                }
                #pragma unroll
                for (int mi = 0; mi < 4; mi++)
                    #pragma unroll
                    for (int nj = 0; nj < 8; nj++)
                        mma_tf32(acc[mi][nj],
                                 af[mi][0], af[mi][1], af[mi][2], af[mi][3],
                                 bf[nj][0], bf[nj][1]);
            }
        }

        const int n0 = sub * 128;
        #pragma unroll
        for (int mi = 0; mi < 4; mi++) {
            const int rl0 = wm * 64 + mi * 16 + grp;
            const int rl1 = rl0 + 8;
            const bool q0 = qm[rl0] != 0;
            const bool q1 = qm[rl1] != 0;
            float rs0 = 0.0f, rs1 = 0.0f;
            #pragma unroll
            for (int nj = 0; nj < 8; nj++) {
                const int col = n0 + wn * 64 + nj * 8 + tg * 2;
                const bool kc0 = km[col] != 0;
                const bool kc1 = km[col + 1] != 0;
                float e00 = __expf((q0 || kc0) ? 1e-9f : acc[mi][nj][0] * inv_temp);
                float e01 = __expf((q0 || kc1) ? 1e-9f : acc[mi][nj][1] * inv_temp);
                float e10 = __expf((q1 || kc0) ? 1e-9f : acc[mi][nj][2] * inv_temp);
                float e11 = __expf((q1 || kc1) ? 1e-9f : acc[mi][nj][3] * inv_temp);
                *(float2*)(attnS + (size_t)(m0r + rl0) * SEQ + col) = make_float2(e00, e01);
                *(float2*)(attnS + (size_t)(m0r + rl1) * SEQ + col) = make_float2(e10, e11);
                rs0 += e00 + e01;
                rs1 += e10 + e11;
            }
            rs0 += __shfl_xor_sync(0xffffffffu, rs0, 1);
            rs0 += __shfl_xor_sync(0xffffffffu, rs0, 2);
            rs1 += __shfl_xor_sync(0xffffffffu, rs1, 1);
            rs1 += __shfl_xor_sync(0xffffffffu, rs1, 2);
            if (tg == 0) {
                SPf[wn * 128 + rl0] += rs0;
                SPf[wn * 128 + rl1] += rs1;
            }
        }
        __syncthreads();
    }

    {
        float s = SPf[tid] + SPf[128 + tid];
        ((float*)(fs + FS_SI))[tid] = 1.0f / s;
    }
    __syncthreads();
    const float* invp = (const float*)(fs + FS_SI);
    float* strip = attnS + (size_t)m0r * SEQ;
    #pragma unroll 4
    for (int i = 0; i < 128; i++) {
        float4* p = (float4*)(strip + (size_t)i * SEQ) + tid;
        float4 v = *p;
        const float s = invp[i];
        v.x *= s; v.y *= s; v.z *= s; v.w *= s;
        *p = v;
    }
}

// ---------------- LayerNorm + NaN guard, one block per row -----------------
__global__ void __launch_bounds__(256) layernorm_kernel(
    const float* __restrict__ X, float* __restrict__ Y,
    const float* __restrict__ gamma, const float* __restrict__ beta)
{
    const int row = blockIdx.x;
    const float* x = X + (size_t)row * DEMB;
    float* y = Y + (size_t)row * DEMB;
    const int tid = threadIdx.x;

    float v[3];
    #pragma unroll
    for (int c = 0; c < 3; c++) v[c] = x[tid + c * 256];

    __shared__ float sred[8];
    float s = v[0] + v[1] + v[2];
    #pragma unroll
    for (int o = 16; o; o >>= 1) s += __shfl_xor_sync(0xffffffffu, s, o);
    if ((tid & 31) == 0) sred[tid >> 5] = s;
    __syncthreads();
    s = 0.0f;
    #pragma unroll
    for (int w = 0; w < 8; w++) s += sred[w];
    const float mu = s * (1.0f / DEMB);
    __syncthreads();

    float d0 = v[0] - mu, d1 = v[1] - mu, d2 = v[2] - mu;
    float sq = d0 * d0 + d1 * d1 + d2 * d2;
    #pragma unroll
    for (int o = 16; o; o >>= 1) sq += __shfl_xor_sync(0xffffffffu, sq, o);
    if ((tid & 31) == 0) sred[tid >> 5] = sq;
    __syncthreads();
    sq = 0.0f;
    #pragma unroll
    for (int w = 0; w < 8; w++) sq += sred[w];
    const float rstd = rsqrtf(sq * (1.0f / DEMB) + 1e-6f);

    #pragma unroll
    for (int c = 0; c < 3; c++) {
        int e = tid + c * 256;
        float o = (v[c] - mu) * rstd * gamma[e] + beta[e];
        if (isnan(o)) o = 0.0f;
        y[e] = o;
    }
}

// ---------------- launch orchestration -------------------------------------
extern "C" void kernel_launch(void* const* d_in, const int* in_sizes, int n_in,
                              void* d_out, int out_size)
{
    const float* q     = (const float*)d_in[0];
    const float* k     = (const float*)d_in[1];
    const float* v     = (const float*)d_in[2];
    const float* Wq    = (const float*)d_in[3];
    const float* Wk    = (const float*)d_in[4];
    const float* Wv    = (const float*)d_in[5];
    const float* Wconv = (const float*)d_in[6];
    const float* bconv = (const float*)d_in[7];
    const float* Wfc   = (const float*)d_in[8];
    const float* gamma = (const float*)d_in[9];
    const float* beta  = (const float*)d_in[10];
    const void*  m1    = d_in[11];
    const void*  m2    = d_in[12];

    float* out = (float*)d_out;

    float *q1, *k1, *q1c, *k1c, *v1, *ctx, *fc, *attn_fb;
    cudaGetSymbolAddress((void**)&q1,  g_q1);
    cudaGetSymbolAddress((void**)&k1,  g_k1);
    cudaGetSymbolAddress((void**)&q1c, g_q1c);
    cudaGetSymbolAddress((void**)&k1c, g_k1c);
    cudaGetSymbolAddress((void**)&v1,  g_v1);
    cudaGetSymbolAddress((void**)&ctx, g_ctx);
    cudaGetSymbolAddress((void**)&fc,  g_fc);
    cudaGetSymbolAddress((void**)&attn_fb, g_attn_fallback);

    float* attn = ((size_t)out_size >= OUT_ELEMS + ATTN_ELEMS) ? (out + OUT_ELEMS)
                                                               : attn_fb;

    // opt-in smem (host attribute set; no allocation)
    cudaFuncSetAttribute(gemm_tc<false>,
                         cudaFuncAttributeMaxDynamicSharedMemorySize, GT_SMEM_BYTES);
    cudaFuncSetAttribute(gemm_tc<true>,
                         cudaFuncAttributeMaxDynamicSharedMemorySize, GT_SMEM_BYTES);
    cudaFuncSetAttribute(fused_scores,
                         cudaFuncAttributeMaxDynamicSharedMemorySize, FS_SMEM_BYTES);

    const int M = BATCH * SEQ;            // 16384
    const float inv_temp = 1.0f / sqrtf((float)DK);

    // 0) canonicalize masks
    canonicalize_masks_kernel<<<MASK_ELEMS / 512, 512>>>(m1, m2);

    // 1) q1 = q @ Wq       (16384 x 512, K=768)
    gemm_tc<false><<<dim3(DK / 128, M / 128, 1), 128, GT_SMEM_BYTES>>>(
        M, DK, DEMB, q, DEMB, 0, 0, Wq, DK, 0, 0, q1, DK, 0, 0,
        1, 1.0f, nullptr, nullptr, 0);
    // 2) k1 = k @ Wk
    gemm_tc<false><<<dim3(DK / 128, M / 128, 1), 128, GT_SMEM_BYTES>>>(
        M, DK, DEMB, k, DEMB, 0, 0, Wk, DK, 0, 0, k1, DK, 0, 0,
        1, 1.0f, nullptr, nullptr, 0);
    // 3) v1 = v @ Wv       (16384 x 1024, K=768)
    gemm_tc<false><<<dim3(DV / 128, M / 128, 1), 128, GT_SMEM_BYTES>>>(
        M, DV, DEMB, v, DEMB, 0, 0, Wv, DV, 0, 0, v1, DV, 0, 0,
        1, 1.0f, nullptr, nullptr, 0);

    // 4/5) conv over sequence axis: q1c[b] = Wconv @ q1[b] + bconv
    const long long sSeq = (long long)SEQ * DK;  // 262144
    gemm_tc<false><<<dim3(SEQ / 128, SEQ / 128, BATCH), 128, GT_SMEM_BYTES>>>(
        SEQ, DK, SEQ, Wconv, SEQ, 0, 0, q1, DK, sSeq, 0, q1c, DK, sSeq, 0,
        1, 1.0f, bconv, nullptr, 0);
    gemm_tc<false><<<dim3(SEQ / 128, SEQ / 128, BATCH), 128, GT_SMEM_BYTES>>>(
        SEQ, DK, SEQ, Wconv, SEQ, 0, 0, k1, DK, sSeq, 0, k1c, DK, sSeq, 0,
        1, 1.0f, bconv, nullptr, 0);

    // 6+7) fused scores + mask + softmax -> normalized attn
    fused_scores<<<dim3(1, SEQ / 128, BATCH * NHEAD), 128, FS_SMEM_BYTES>>>(
        q1c, k1c, attn, inv_temp);

    // 8) ctx[b,h] = attn[b,h] @ Vh[b,h]   (512x128, K=512) x 256
    const long long sAttnB = (long long)NHEAD * SEQ * SEQ;
    const long long sAttnH = (long long)SEQ * SEQ;
    const long long sVB = (long long)SEQ * DV;
    gemm_tc<false><<<dim3((DV / NHEAD) / 128, SEQ / 128, BATCH * NHEAD), 128, GT_SMEM_BYTES>>>(
        SEQ, DV / NHEAD, SEQ,
        attn, SEQ, sAttnB, sAttnH,
        v1, DV, sVB, DV / NHEAD,
        ctx, DV, sVB, DV / NHEAD,
        NHEAD, 1.0f, nullptr, nullptr, 0);

    // 9) fc = ctx @ Wfc + q (residual)   (16384 x 768, K=1024)
    gemm_tc<false><<<dim3(DEMB / 128, M / 128, 1), 128, GT_SMEM_BYTES>>>(
        M, DEMB, DV, ctx, DV, 0, 0, Wfc, DEMB, 0, 0, fc, DEMB, 0, 0,
        1, 1.0f, nullptr, q, DEMB);

    // 10) LayerNorm + NaN guard -> out
    layernorm_kernel<<<M, 256>>>(fc, out, gamma, beta);
}

// round 16
// speedup vs baseline: 1.0093x; 1.0093x over previous
#include <cuda_runtime.h>
#include <stdint.h>
#include <math.h>

#define BATCH 32
#define SEQ   512
#define DEMB  768
#define DK    512
#define DV    1024
#define NHEAD 8

#define OUT_ELEMS  ((size_t)BATCH*SEQ*DEMB)          // 12,582,912
#define ATTN_ELEMS ((size_t)BATCH*NHEAD*SEQ*SEQ)     // 67,108,864
#define MASK_ELEMS (BATCH*SEQ)                       // 16,384

// ---------------- scratch (static __device__, no runtime allocs) ----------
__device__ float g_q1 [(size_t)BATCH*SEQ*DK];
__device__ float g_k1 [(size_t)BATCH*SEQ*DK];
__device__ float g_q1c[(size_t)BATCH*SEQ*DK];
__device__ float g_k1c[(size_t)BATCH*SEQ*DK];
__device__ float g_v1 [(size_t)BATCH*SEQ*DV];
__device__ float g_ctx[(size_t)BATCH*SEQ*DV];
__device__ float g_fc [(size_t)BATCH*SEQ*DEMB];
__device__ uint8_t g_m1c[MASK_ELEMS];
__device__ uint8_t g_m2c[MASK_ELEMS];
__device__ float g_attn_fallback[ATTN_ELEMS];

// ---------------- mask canonicalization ------------------------------------
__device__ __forceinline__ int detect_mask_dtype(const uint32_t* w) {
    bool low_bf16 = false, f32 = false, topbytes = false;
    #pragma unroll 8
    for (int i = 0; i < 64; i++) {
        uint32_t x = w[i];
        if ((x & 0xFFFFu) == 0x3F80u) low_bf16 = true;
        if (x == 0x3F800000u)         f32 = true;
        if (x & 0xFFFFFF00u)          topbytes = true;
    }
    if (low_bf16) return 3;
    if (f32)      return 2;
    if (topbytes) return 1;
    return 0;                 // int32
}

__global__ void canonicalize_masks_kernel(const void* m1, const void* m2) {
    const int i = blockIdx.x * blockDim.x + threadIdx.x;
    const int code1 = detect_mask_dtype((const uint32_t*)m1);
    const int code2 = detect_mask_dtype((const uint32_t*)m2);

    uint8_t v1, v2;
    switch (code1) {
        case 0:  v1 = ((const int32_t*) m1)[i] != 0; break;
        case 1:  v1 = ((const uint8_t*) m1)[i] != 0; break;
        case 2:  v1 = ((const uint32_t*)m1)[i] != 0; break;
        default: v1 = ((const uint16_t*)m1)[i] != 0; break;
    }
    switch (code2) {
        case 0:  v2 = ((const int32_t*) m2)[i] != 0; break;
        case 1:  v2 = ((const uint8_t*) m2)[i] != 0; break;
        case 2:  v2 = ((const uint32_t*)m2)[i] != 0; break;
        default: v2 = ((const uint16_t*)m2)[i] != 0; break;
    }
    g_m1c[i] = v1;
    g_m2c[i] = v2;
}

// ---------------- shared PTX helpers ----------------------------------------
__device__ __forceinline__ void cpa16(uint32_t dst, const void* src) {
    asm volatile("cp.async.cg.shared.global [%0], [%1], 16;" :: "r"(dst), "l"(src));
}
__device__ __forceinline__ void cpa_commit() {
    asm volatile("cp.async.commit_group;");
}
__device__ __forceinline__ void cpa_wait1() {
    asm volatile("cp.async.wait_group 1;");
}

__device__ __forceinline__ void mma_tf32(float c[4],
    uint32_t a0, uint32_t a1, uint32_t a2, uint32_t a3,
    uint32_t b0, uint32_t b1)
{
    asm volatile(
        "mma.sync.aligned.m16n8k8.row.col.f32.tf32.tf32.f32 "
        "{%0,%1,%2,%3}, {%4,%5,%6,%7}, {%8,%9}, {%0,%1,%2,%3};"
        : "+f"(c[0]), "+f"(c[1]), "+f"(c[2]), "+f"(c[3])
        : "r"(a0), "r"(a1), "r"(a2), "r"(a3), "r"(b0), "r"(b1));
}

// ldmatrix x4 over 32-bit elements: four 8x8(b16x2) matrices; lane supplies the
// byte address of one 16B row-chunk. For tf32 fragments each lane receives
// element (lane>>2, lane&3) of its matrix.
__device__ __forceinline__ void ldsm4(uint32_t& r0, uint32_t& r1,
                                      uint32_t& r2, uint32_t& r3, uint32_t addr)
{
    asm volatile("ldmatrix.sync.aligned.m8n8.x4.shared.b16 {%0,%1,%2,%3}, [%4];"
                 : "=r"(r0), "=r"(r1), "=r"(r2), "=r"(r3) : "r"(addr));
}

// ---------------- TF32 tensor-core batched GEMM (BK=32, 3-stage, ldmatrix) --
// C[z] = alpha * A[z] @ B[z] (+rowBias) (+resid), row-major, fp32 accumulate.
// TRB=false: B is K x N. TRB=true: B is N x K (C = A @ B^T).
// Requires M,N % 128 == 0, K % 32 == 0, K >= 64 (all call sites comply).
// Block 128x128xBK32, 128 threads, 4 warps of 64x64.
// smem stage = two BK=16 sub-tiles:
//   A / B(TR): [row][16] packed, chunk swizzle ch' = ch ^ ((row>>1)&3)
//   B(nonTR):  [k][128] packed, chunk swizzle  cn' = cn ^ (2*(k&3))
// Fragment loads: A via ldmatrix.x4 (4 instr/kk vs 16 LDS); B(TR) via
// ldmatrix.x4 (4 vs 16); B(nonTR) scalar LDS (layout not ldmatrix-able).
#define GT_STAGE_W 8192              // words per stage (A 4096 + B 4096)
#define GT_SMEM_BYTES (3 * GT_STAGE_W * 4)

template<bool TRB>
__global__ void __launch_bounds__(128, 2) gemm_tc(
    int M, int N, int K,
    const float* __restrict__ A, int lda, long long sAb, long long sAh,
    const float* __restrict__ B, int ldb, long long sBb, long long sBh,
    float* __restrict__ C, int ldc, long long sCb, long long sCh,
    int H, float alpha,
    const float* __restrict__ rowBias,
    const float* __restrict__ resid, int ldr)
{
    extern __shared__ __align__(16) uint32_t dsm[];
    uint32_t* Asm = dsm;                         // stage s at s*GT_STAGE_W
    uint32_t* Bsm = dsm + 4096;                  // stage s at s*GT_STAGE_W + 4096

    const int z = blockIdx.z;
    const int b = z / H, h = z % H;
    A += b * sAb + h * sAh;
    B += b * sBb + h * sBh;
    C += b * sCb + h * sCh;

    const int m0 = blockIdx.y * 128;
    const int n0 = blockIdx.x * 128;
    const int tid  = threadIdx.x;
    const int wid  = tid >> 5;
    const int lane = tid & 31;
    const int wm = wid & 1;
    const int wn = wid >> 1;
    const int grp = lane >> 2;
    const int tg  = lane & 3;
    // ldmatrix lane decomposition
    const int quad = lane >> 3, jr = lane & 7;
    const int qh = quad >> 1, ql = quad & 1;

    const uint32_t asAddr = (uint32_t)__cvta_generic_to_shared(Asm);
    const uint32_t bsAddr = (uint32_t)__cvta_generic_to_shared(Bsm);

    float acc[4][8][4] = {};

    // loader: 8 cpa16/thread per operand per BK=32 tile
    auto load_tile = [&](int s, int k0) {
        const uint32_t sb = (uint32_t)(s * GT_STAGE_W);
        #pragma unroll
        for (int j = 0; j < 8; j++) {
            const int c = tid + j * 128;          // 0..1023
            const int kt = c >> 9;                // sub-tile 0/1
            const int pos = c & 511;
            const int row = pos >> 2, ch = pos & 3;
            const uint32_t adst = sb + (uint32_t)(kt * 2048 + row * 16 +
                                    ((ch ^ ((row >> 1) & 3)) << 2));
            cpa16(asAddr + adst * 4u,
                  A + (size_t)(m0 + row) * lda + k0 + kt * 16 + ch * 4);
            if (TRB) {
                cpa16(bsAddr + adst * 4u,
                      B + (size_t)(n0 + row) * ldb + k0 + kt * 16 + ch * 4);
            } else {
                const int bk = pos >> 5, bcn = pos & 31;
                const uint32_t bdst = sb + (uint32_t)(kt * 2048 + bk * 128 +
                                        ((bcn ^ (2 * (bk & 3))) << 2));
                cpa16(bsAddr + bdst * 4u,
                      B + (size_t)(k0 + kt * 16 + bk) * ldb + n0 + bcn * 4);
            }
        }
    };

    // ---- ldmatrix per-lane address bases (bytes within a BK16 sub-tile)
    // A, matrix quads: row = wm*64 + mi*16 + ql*8 + jr ; chunk = c0 + qh
    uint32_t aByte[4]; int aSw[4];
    #pragma unroll
    for (int mi = 0; mi < 4; mi++) {
        const int row = wm * 64 + mi * 16 + ql * 8 + jr;
        aByte[mi] = (uint32_t)(row * 64);
        aSw[mi]   = (row >> 1) & 3;
    }
    // B(TR), nj-pairs: row = wn*64 + njp*16 + qh*8 + jr ; chunk = c0 + ql
    uint32_t bByte[4]; int bSw[4];
    #pragma unroll
    for (int njp = 0; njp < 4; njp++) {
        const int row = wn * 64 + njp * 16 + qh * 8 + jr;
        bByte[njp] = (uint32_t)(row * 64);
        bSw[njp]   = (row >> 1) & 3;
    }
    // B(nonTR) scalar path
    int bqF[8];
    #pragma unroll
    for (int nj = 0; nj < 8; nj++) {
        const int nr = wn * 64 + nj * 8 + grp;
        const int cn = nr >> 2, nl = nr & 3;
        bqF[nj] = ((cn ^ (2 * tg)) << 2) + nl;
    }

    const int nIter = K >> 5;   // >= 2 at all call sites

    load_tile(0, 0);  cpa_commit();
    load_tile(1, 32); cpa_commit();

    int stage = 0;
    for (int it = 0; it < nIter; it++) {
        cpa_wait1();              // tile `it` resident for this thread
        __syncthreads();          // visible to all; compute(it-1) done by all

        const int nt = it + 2;    // uniform commit cadence (empty ok)
        int nstage = stage + 2; if (nstage >= 3) nstage -= 3;
        if (nt < nIter) load_tile(nstage, nt * 32);
        cpa_commit();

        const uint32_t aT = asAddr + (uint32_t)(stage * GT_STAGE_W) * 4u;
        const uint32_t bT = bsAddr + (uint32_t)(stage * GT_STAGE_W) * 4u;
        const uint32_t* BbW = Bsm + stage * GT_STAGE_W;

        #pragma unroll
        for (int kt = 0; kt < 2; kt++) {
            const uint32_t aK = aT + (uint32_t)(kt * 8192);
            const uint32_t bK = bT + (uint32_t)(kt * 8192);
            const uint32_t* Bb = BbW + kt * 2048;
            #pragma unroll
            for (int kk = 0; kk < 2; kk++) {
                const int c0 = kk * 2;
                uint32_t af[4][4];
                #pragma unroll
                for (int mi = 0; mi < 4; mi++)
                    ldsm4(af[mi][0], af[mi][1], af[mi][2], af[mi][3],
                          aK + aByte[mi] + (uint32_t)(((c0 + qh) ^ aSw[mi]) << 4));
                uint32_t bf[8][2];
                if (TRB) {
                    #pragma unroll
                    for (int njp = 0; njp < 4; njp++)
                        ldsm4(bf[2 * njp][0], bf[2 * njp][1],
                              bf[2 * njp + 1][0], bf[2 * njp + 1][1],
                              bK + bByte[njp] + (uint32_t)(((c0 + ql) ^ bSw[njp]) << 4));
                } else {
                    const int ko = kk * 8;
                    #pragma unroll
                    for (int nj = 0; nj < 8; nj++) {
                        bf[nj][0] = Bb[(ko + tg) * 128 + bqF[nj]];
                        bf[nj][1] = Bb[(ko + tg + 4) * 128 + bqF[nj]];
                    }
                }
                #pragma unroll
                for (int mi = 0; mi < 4; mi++)
                    #pragma unroll
                    for (int nj = 0; nj < 8; nj++)
                        mma_tf32(acc[mi][nj],
                                 af[mi][0], af[mi][1], af[mi][2], af[mi][3],
                                 bf[nj][0], bf[nj][1]);
            }
        }
        if (++stage == 3) stage = 0;
    }

    // ---- epilogue
    #pragma unroll
    for (int mi = 0; mi < 4; mi++) {
        const int row = m0 + wm * 64 + mi * 16 + grp;
        const float bias0 = rowBias ? rowBias[row] : 0.0f;
        const float bias1 = rowBias ? rowBias[row + 8] : 0.0f;
        #pragma unroll
        for (int nj = 0; nj < 8; nj++) {
            const int col = n0 + wn * 64 + nj * 8 + tg * 2;
            float2 o0, o1;
            o0.x = acc[mi][nj][0] * alpha + bias0;
            o0.y = acc[mi][nj][1] * alpha + bias0;
            o1.x = acc[mi][nj][2] * alpha + bias1;
            o1.y = acc[mi][nj][3] * alpha + bias1;
            if (resid) {
                float2 r0 = *(const float2*)(resid + (size_t)row * ldr + col);
                float2 r1 = *(const float2*)(resid + (size_t)(row + 8) * ldr + col);
                o0.x += r0.x; o0.y += r0.y;
                o1.x += r1.x; o1.y += r1.y;
            }
            *(float2*)(C + (size_t)row * ldc + col)       = o0;
            *(float2*)(C + (size_t)(row + 8) * ldc + col) = o1;
        }
    }
}

// ---------------- fused scores + mask + softmax (ldmatrix fragments) --------
#define FS_SA  0
#define FS_SB  8192
#define FS_SP  24576
#define FS_SI  24832
#define FS_SQM 24960
#define FS_SKM 24992
#define FS_SMEM_BYTES (25120 * 4)

__device__ __forceinline__ void cpa_wait1_fs() {
    asm volatile("cp.async.wait_group 1;");
}

__global__ void __launch_bounds__(128, 2) fused_scores(
    const float* __restrict__ Qc, const float* __restrict__ Kc,
    float* __restrict__ attn, float inv_temp)
{
    extern __shared__ __align__(16) uint32_t fs[];
    const int z = blockIdx.z;            // b*8+h
    const int b = z >> 3, h = z & 7;
    const int m0r = blockIdx.y * 128;
    const float* Ag = Qc + (size_t)b * (SEQ * DK) + (size_t)h * 64;
    const float* Bg = Kc + (size_t)b * (SEQ * DK) + (size_t)h * 64;
    float* attnS = attn + (size_t)z * (SEQ * SEQ);

    const int tid = threadIdx.x, wid = tid >> 5, lane = tid & 31;
    const int wm = wid & 1, wn = wid >> 1;
    const int grp = lane >> 2, tg = lane & 3;
    const int quad = lane >> 3, jr = lane & 7;
    const int qh = quad >> 1, ql = quad & 1;

    const uint32_t sbase = (uint32_t)__cvta_generic_to_shared(fs);

    #pragma unroll
    for (int j = 0; j < 16; j++) {
        const int c = tid + j * 128;
        const int kt = c >> 9, row = (c >> 2) & 127, ch = c & 3;
        const uint32_t dst = (uint32_t)(FS_SA + kt * 2048 + row * 16 +
                                        ((ch ^ ((row >> 1) & 3)) << 2));
        cpa16(sbase + dst * 4u, Ag + (size_t)(m0r + row) * DK + kt * 16 + ch * 4);
    }
    #pragma unroll
    for (int j = 0; j < 16; j++) {
        const int c = tid + j * 128;
        const int kt = c >> 9, row = (c >> 2) & 127, ch = c & 3;
        const uint32_t dst = (uint32_t)(FS_SB + kt * 2048 + row * 16 +
                                        ((ch ^ ((row >> 1) & 3)) << 2));
        cpa16(sbase + dst * 4u, Bg + (size_t)row * DK + kt * 16 + ch * 4);
    }
    cpa_commit();

    ((uint8_t*)(fs + FS_SQM))[tid] = g_m1c[b * SEQ + m0r + tid];
    fs[FS_SP + tid] = 0;
    fs[FS_SP + 128 + tid] = 0;
    {
        uint8_t* km = (uint8_t*)(fs + FS_SKM);
        #pragma unroll
        for (int j = 0; j < 4; j++) km[tid + j * 128] = g_m2c[b * SEQ + tid + j * 128];
    }

    // ldmatrix per-lane bases (bytes within a BK16 sub-tile)
    uint32_t aByte[4]; int aSw[4];
    #pragma unroll
    for (int mi = 0; mi < 4; mi++) {
        const int row = wm * 64 + mi * 16 + ql * 8 + jr;
        aByte[mi] = (uint32_t)(row * 64);
        aSw[mi]   = (row >> 1) & 3;
    }
    uint32_t bByte[4]; int bSw[4];
    #pragma unroll
    for (int njp = 0; njp < 4; njp++) {
        const int row = wn * 64 + njp * 16 + qh * 8 + jr;
        bByte[njp] = (uint32_t)(row * 64);
        bSw[njp]   = (row >> 1) & 3;
    }

    float* SPf = (float*)(fs + FS_SP);
    const uint8_t* qm = (const uint8_t*)(fs + FS_SQM);
    const uint8_t* km = (const uint8_t*)(fs + FS_SKM);

    for (int sub = 0; sub < 4; sub++) {
        if (sub < 3) {
            const int n0n = (sub + 1) * 128;
            const int bufn = (sub + 1) & 1;
            #pragma unroll
            for (int j = 0; j < 16; j++) {
                const int c = tid + j * 128;
                const int kt = c >> 9, row = (c >> 2) & 127, ch = c & 3;
                const uint32_t dst = (uint32_t)(FS_SB + bufn * 8192 + kt * 2048 +
                                                row * 16 + ((ch ^ ((row >> 1) & 3)) << 2));
                cpa16(sbase + dst * 4u, Bg + (size_t)(n0n + row) * DK + kt * 16 + ch * 4);
            }
        }
        cpa_commit();
        cpa_wait1_fs();
        __syncthreads();

        float acc[4][8][4] = {};
        const int buf = sub & 1;

        #pragma unroll
        for (int kt = 0; kt < 4; kt++) {
            const uint32_t aK = sbase + (uint32_t)((FS_SA + kt * 2048) * 4);
            const uint32_t bK = sbase + (uint32_t)((FS_SB + buf * 8192 + kt * 2048) * 4);
            #pragma unroll
            for (int kk = 0; kk < 2; kk++) {
                const int c0 = kk * 2;
                uint32_t af[4][4];
                #pragma unroll
                for (int mi = 0; mi < 4; mi++)
                    ldsm4(af[mi][0], af[mi][1], af[mi][2], af[mi][3],
                          aK + aByte[mi] + (uint32_t)(((c0 + qh) ^ aSw[mi]) << 4));
                uint32_t bf[8][2];
                #pragma unroll
                for (int njp = 0; njp < 4; njp++)
                    ldsm4(bf[2 * njp][0], bf[2 * njp][1],
                          bf[2 * njp + 1][0], bf[2 * njp + 1][1],
                          bK + bByte[njp] + (uint32_t)(((c0 + ql) ^ bSw[njp]) << 4));
                #pragma unroll
                for (int mi = 0; mi < 4; mi++)
                    #pragma unroll
                    for (int nj = 0; nj < 8; nj++)
                        mma_tf32(acc[mi][nj],
                                 af[mi][0], af[mi][1], af[mi][2], af[mi][3],
                                 bf[nj][0], bf[nj][1]);
            }
        }

        const int n0 = sub * 128;
        #pragma unroll
        for (int mi = 0; mi < 4; mi++) {
            const int rl0 = wm * 64 + mi * 16 + grp;
            const int rl1 = rl0 + 8;
            const bool q0 = qm[rl0] != 0;
            const bool q1 = qm[rl1] != 0;
            float rs0 = 0.0f, rs1 = 0.0f;
            #pragma unroll
            for (int nj = 0; nj < 8; nj++) {
                const int col = n0 + wn * 64 + nj * 8 + tg * 2;
                const bool kc0 = km[col] != 0;
                const bool kc1 = km[col + 1] != 0;
                float e00 = __expf((q0 || kc0) ? 1e-9f : acc[mi][nj][0] * inv_temp);
                float e01 = __expf((q0 || kc1) ? 1e-9f : acc[mi][nj][1] * inv_temp);
                float e10 = __expf((q1 || kc0) ? 1e-9f : acc[mi][nj][2] * inv_temp);
                float e11 = __expf((q1 || kc1) ? 1e-9f : acc[mi][nj][3] * inv_temp);
                *(float2*)(attnS + (size_t)(m0r + rl0) * SEQ + col) = make_float2(e00, e01);
                *(float2*)(attnS + (size_t)(m0r + rl1) * SEQ + col) = make_float2(e10, e11);
                rs0 += e00 + e01;
                rs1 += e10 + e11;
            }
            rs0 += __shfl_xor_sync(0xffffffffu, rs0, 1);
            rs0 += __shfl_xor_sync(0xffffffffu, rs0, 2);
            rs1 += __shfl_xor_sync(0xffffffffu, rs1, 1);
            rs1 += __shfl_xor_sync(0xffffffffu, rs1, 2);
            if (tg == 0) {
                SPf[wn * 128 + rl0] += rs0;
                SPf[wn * 128 + rl1] += rs1;
            }
        }
        __syncthreads();
    }

    {
        float s = SPf[tid] + SPf[128 + tid];
        ((float*)(fs + FS_SI))[tid] = 1.0f / s;
    }
    __syncthreads();
    const float* invp = (const float*)(fs + FS_SI);
    float* strip = attnS + (size_t)m0r * SEQ;
    #pragma unroll 4
    for (int i = 0; i < 128; i++) {
        float4* p = (float4*)(strip + (size_t)i * SEQ) + tid;
        float4 v = *p;
        const float s = invp[i];
        v.x *= s; v.y *= s; v.z *= s; v.w *= s;
        *p = v;
    }
}

// ---------------- LayerNorm + NaN guard, one block per row -----------------
__global__ void __launch_bounds__(256) layernorm_kernel(
    const float* __restrict__ X, float* __restrict__ Y,
    const float* __restrict__ gamma, const float* __restrict__ beta)
{
    const int row = blockIdx.x;
    const float* x = X + (size_t)row * DEMB;
    float* y = Y + (size_t)row * DEMB;
    const int tid = threadIdx.x;

    float v[3];
    #pragma unroll
    for (int c = 0; c < 3; c++) v[c] = x[tid + c * 256];

    __shared__ float sred[8];
    float s = v[0] + v[1] + v[2];
    #pragma unroll
    for (int o = 16; o; o >>= 1) s += __shfl_xor_sync(0xffffffffu, s, o);
    if ((tid & 31) == 0) sred[tid >> 5] = s;
    __syncthreads();
    s = 0.0f;
    #pragma unroll
    for (int w = 0; w < 8; w++) s += sred[w];
    const float mu = s * (1.0f / DEMB);
    __syncthreads();

    float d0 = v[0] - mu, d1 = v[1] - mu, d2 = v[2] - mu;
    float sq = d0 * d0 + d1 * d1 + d2 * d2;
    #pragma unroll
    for (int o = 16; o; o >>= 1) sq += __shfl_xor_sync(0xffffffffu, sq, o);
    if ((tid & 31) == 0) sred[tid >> 5] = sq;
    __syncthreads();
    sq = 0.0f;
    #pragma unroll
    for (int w = 0; w < 8; w++) sq += sred[w];
    const float rstd = rsqrtf(sq * (1.0f / DEMB) + 1e-6f);

    #pragma unroll
    for (int c = 0; c < 3; c++) {
        int e = tid + c * 256;
        float o = (v[c] - mu) * rstd * gamma[e] + beta[e];
        if (isnan(o)) o = 0.0f;
        y[e] = o;
    }
}

// ---------------- launch orchestration -------------------------------------
extern "C" void kernel_launch(void* const* d_in, const int* in_sizes, int n_in,
                              void* d_out, int out_size)
{
    const float* q     = (const float*)d_in[0];
    const float* k     = (const float*)d_in[1];
    const float* v     = (const float*)d_in[2];
    const float* Wq    = (const float*)d_in[3];
    const float* Wk    = (const float*)d_in[4];
    const float* Wv    = (const float*)d_in[5];
    const float* Wconv = (const float*)d_in[6];
    const float* bconv = (const float*)d_in[7];
    const float* Wfc   = (const float*)d_in[8];
    const float* gamma = (const float*)d_in[9];
    const float* beta  = (const float*)d_in[10];
    const void*  m1    = d_in[11];
    const void*  m2    = d_in[12];

    float* out = (float*)d_out;

    float *q1, *k1, *q1c, *k1c, *v1, *ctx, *fc, *attn_fb;
    cudaGetSymbolAddress((void**)&q1,  g_q1);
    cudaGetSymbolAddress((void**)&k1,  g_k1);
    cudaGetSymbolAddress((void**)&q1c, g_q1c);
    cudaGetSymbolAddress((void**)&k1c, g_k1c);
    cudaGetSymbolAddress((void**)&v1,  g_v1);
    cudaGetSymbolAddress((void**)&ctx, g_ctx);
    cudaGetSymbolAddress((void**)&fc,  g_fc);
    cudaGetSymbolAddress((void**)&attn_fb, g_attn_fallback);

    float* attn = ((size_t)out_size >= OUT_ELEMS + ATTN_ELEMS) ? (out + OUT_ELEMS)
                                                               : attn_fb;

    // opt-in smem (host attribute set; no allocation)
    cudaFuncSetAttribute(gemm_tc<false>,
                         cudaFuncAttributeMaxDynamicSharedMemorySize, GT_SMEM_BYTES);
    cudaFuncSetAttribute(gemm_tc<true>,
                         cudaFuncAttributeMaxDynamicSharedMemorySize, GT_SMEM_BYTES);
    cudaFuncSetAttribute(fused_scores,
                         cudaFuncAttributeMaxDynamicSharedMemorySize, FS_SMEM_BYTES);

    const int M = BATCH * SEQ;            // 16384
    const float inv_temp = 1.0f / sqrtf((float)DK);

    // 0) canonicalize masks
    canonicalize_masks_kernel<<<MASK_ELEMS / 512, 512>>>(m1, m2);

    // 1) q1 = q @ Wq       (16384 x 512, K=768)
    gemm_tc<false><<<dim3(DK / 128, M / 128, 1), 128, GT_SMEM_BYTES>>>(
        M, DK, DEMB, q, DEMB, 0, 0, Wq, DK, 0, 0, q1, DK, 0, 0,
        1, 1.0f, nullptr, nullptr, 0);
    // 2) k1 = k @ Wk
    gemm_tc<false><<<dim3(DK / 128, M / 128, 1), 128, GT_SMEM_BYTES>>>(
        M, DK, DEMB, k, DEMB, 0, 0, Wk, DK, 0, 0, k1, DK, 0, 0,
        1, 1.0f, nullptr, nullptr, 0);
    // 3) v1 = v @ Wv       (16384 x 1024, K=768)
    gemm_tc<false><<<dim3(DV / 128, M / 128, 1), 128, GT_SMEM_BYTES>>>(
        M, DV, DEMB, v, DEMB, 0, 0, Wv, DV, 0, 0, v1, DV, 0, 0,
        1, 1.0f, nullptr, nullptr, 0);

    // 4/5) conv over sequence axis: q1c[b] = Wconv @ q1[b] + bconv
    const long long sSeq = (long long)SEQ * DK;  // 262144
    gemm_tc<false><<<dim3(SEQ / 128, SEQ / 128, BATCH), 128, GT_SMEM_BYTES>>>(
        SEQ, DK, SEQ, Wconv, SEQ, 0, 0, q1, DK, sSeq, 0, q1c, DK, sSeq, 0,
        1, 1.0f, bconv, nullptr, 0);
    gemm_tc<false><<<dim3(SEQ / 128, SEQ / 128, BATCH), 128, GT_SMEM_BYTES>>>(
        SEQ, DK, SEQ, Wconv, SEQ, 0, 0, k1, DK, sSeq, 0, k1c, DK, sSeq, 0,
        1, 1.0f, bconv, nullptr, 0);

    // 6+7) fused scores + mask + softmax -> normalized attn
    fused_scores<<<dim3(1, SEQ / 128, BATCH * NHEAD), 128, FS_SMEM_BYTES>>>(
        q1c, k1c, attn, inv_temp);

    // 8) ctx[b,h] = attn[b,h] @ Vh[b,h]   (512x128, K=512) x 256
    const long long sAttnB = (long long)NHEAD * SEQ * SEQ;
    const long long sAttnH = (long long)SEQ * SEQ;
    const long long sVB = (long long)SEQ * DV;
    gemm_tc<false><<<dim3((DV / NHEAD) / 128, SEQ / 128, BATCH * NHEAD), 128, GT_SMEM_BYTES>>>(
        SEQ, DV / NHEAD, SEQ,
        attn, SEQ, sAttnB, sAttnH,
        v1, DV, sVB, DV / NHEAD,
        ctx, DV, sVB, DV / NHEAD,
        NHEAD, 1.0f, nullptr, nullptr, 0);

    // 9) fc = ctx @ Wfc + q (residual)   (16384 x 768, K=1024)
    gemm_tc<false><<<dim3(DEMB / 128, M / 128, 1), 128, GT_SMEM_BYTES>>>(
        M, DEMB, DV, ctx, DV, 0, 0, Wfc, DEMB, 0, 0, fc, DEMB, 0, 0,
        1, 1.0f, nullptr, q, DEMB);

    // 10) LayerNorm + NaN guard -> out
    layernorm_kernel<<<M, 256>>>(fc, out, gamma, beta);
}